// round 1
// baseline (speedup 1.0000x reference)
#include <cuda_runtime.h>

// Inverse of phi(t) = sum_k w_k exp(-s_k t) via precomputed cubic-Hermite
// inverse table + pure interpolation main pass.
//
// Kernel 1 (build): one warp per table knot, one mixture component per lane
//   (K == 32 == warpSize). Log-space Newton on F(t) = ln(phi) - ln(y):
//   convex (logsumexp of affine), monotone convergence from t=0, near-linear
//   in the tail so it converges fast everywhere. Stores (t*, dt/dy = -1/phi').
// Kernel 2 (solve): per point: index into table, cubic Hermite interpolation.
//   Memory-bound: 8MB read + 8MB write; 64KB table lives in L1.

#define NT 8192
#define Y0 0.05f
#define Y1 0.95f
#define NEWTON_ITERS 20
#define KMIX 32

__device__ float2 g_tab[NT];

__global__ void __launch_bounds__(256)
phiinv_build_kernel(const float* __restrict__ w_logits,
                    const float* __restrict__ s_raw) {
    const int lane = threadIdx.x & 31;
    const int warp = (blockIdx.x * blockDim.x + threadIdx.x) >> 5;
    if (warp >= NT) return;   // whole warps exit together

    // --- per-lane mixture params (softmax weights, softplus rates) ---
    float lw = w_logits[lane];
    float m = lw;
    #pragma unroll
    for (int o = 16; o; o >>= 1) m = fmaxf(m, __shfl_xor_sync(0xffffffffu, m, o));
    float ew = __expf(lw - m);
    float wsum = ew;
    #pragma unroll
    for (int o = 16; o; o >>= 1) wsum += __shfl_xor_sync(0xffffffffu, wsum, o);
    float w = ew / wsum;

    float x = s_raw[lane];
    // numerically stable softplus: max(x,0) + log1p(exp(-|x|))
    float s = fmaxf(x, 0.0f) + log1pf(__expf(-fabsf(x))) + 0.1f;

    // --- log-space Newton for this knot's y ---
    const float dy = (Y1 - Y0) / (float)(NT - 1);
    const float yt = Y0 + (float)warp * dy;
    const float ly = __logf(yt);

    float t = 0.0f;
    #pragma unroll 1
    for (int it = 0; it < NEWTON_ITERS; ++it) {
        float ek = __expf(-t * s);
        float a = w * ek;        // contributes to f  = phi(t)
        float b = a * s;         // contributes to fp = -phi'(t) > 0
        #pragma unroll
        for (int o = 16; o; o >>= 1) {
            a += __shfl_xor_sync(0xffffffffu, a, o);
            b += __shfl_xor_sync(0xffffffffu, b, o);
        }
        // F = ln f - ln y ; F' = -b/a ; Newton: t += (ln f - ln y) * a / b
        float g = __logf(a) - ly;
        t = fmaxf(fmaf(g, a / b, t), 0.0f);
    }

    // final derivative at the converged root
    float ek = __expf(-t * s);
    float a = w * ek;
    float b = a * s;
    #pragma unroll
    for (int o = 16; o; o >>= 1) {
        a += __shfl_xor_sync(0xffffffffu, a, o);
        b += __shfl_xor_sync(0xffffffffu, b, o);
    }
    if (lane == 0) {
        // dt/dy = 1/phi'(t) = -1/b
        g_tab[warp] = make_float2(t, -1.0f / b);
    }
}

__global__ void __launch_bounds__(256)
phiinv_solve_kernel(const float* __restrict__ y,
                    float* __restrict__ out, int n) {
    const float inv_dy = (float)(NT - 1) / (Y1 - Y0);
    const float dy     = (Y1 - Y0) / (float)(NT - 1);

    int i = (blockIdx.x * blockDim.x + threadIdx.x) * 4;
    if (i + 3 < n) {
        float4 yv = *reinterpret_cast<const float4*>(y + i);
        float yy[4] = {yv.x, yv.y, yv.z, yv.w};
        float r[4];
        #pragma unroll
        for (int c = 0; c < 4; ++c) {
            float u = (yy[c] - Y0) * inv_dy;
            u = fminf(fmaxf(u, 0.0f), (float)(NT - 1));
            int j = min((int)u, NT - 2);
            float fr = u - (float)j;
            float2 A = g_tab[j];
            float2 B = g_tab[j + 1];
            float fr2 = fr * fr;
            float fr3 = fr2 * fr;
            float h00 = 2.0f * fr3 - 3.0f * fr2 + 1.0f;
            float h01 = 3.0f * fr2 - 2.0f * fr3;
            float h10 = fr3 - 2.0f * fr2 + fr;
            float h11 = fr3 - fr2;
            r[c] = h00 * A.x + h01 * B.x + dy * (h10 * A.y + h11 * B.y);
        }
        *reinterpret_cast<float4*>(out + i) = make_float4(r[0], r[1], r[2], r[3]);
    } else {
        // scalar tail (N=2M is divisible by 4; kept for safety)
        for (int k = i; k < n; ++k) {
            float u = (y[k] - Y0) * inv_dy;
            u = fminf(fmaxf(u, 0.0f), (float)(NT - 1));
            int j = min((int)u, NT - 2);
            float fr = u - (float)j;
            float2 A = g_tab[j];
            float2 B = g_tab[j + 1];
            float fr2 = fr * fr;
            float fr3 = fr2 * fr;
            float h00 = 2.0f * fr3 - 3.0f * fr2 + 1.0f;
            float h01 = 3.0f * fr2 - 2.0f * fr3;
            float h10 = fr3 - 2.0f * fr2 + fr;
            float h11 = fr3 - fr2;
            out[k] = h00 * A.x + h01 * B.x + dy * (h10 * A.y + h11 * B.y);
        }
    }
}

extern "C" void kernel_launch(void* const* d_in, const int* in_sizes, int n_in,
                              void* d_out, int out_size) {
    // Identify y as the large input; the two size-K inputs keep metadata order
    // (w_logits, then s_raw).
    int yi = 0;
    for (int i = 1; i < n_in; ++i)
        if (in_sizes[i] > in_sizes[yi]) yi = i;
    int small[2], ns = 0;
    for (int i = 0; i < n_in && ns < 2; ++i)
        if (i != yi) small[ns++] = i;

    const float* y  = (const float*)d_in[yi];
    const float* wl = (const float*)d_in[small[0]];
    const float* sr = (const float*)d_in[small[1]];
    float* out = (float*)d_out;
    const int n = in_sizes[yi];

    // Build inverse table: NT warps
    const int build_threads = 256;
    const int build_blocks  = (NT * 32 + build_threads - 1) / build_threads;
    phiinv_build_kernel<<<build_blocks, build_threads>>>(wl, sr);

    // Interpolate all points: 4 per thread
    const int work = (n + 3) / 4;
    const int solve_threads = 256;
    const int solve_blocks  = (work + solve_threads - 1) / solve_threads;
    phiinv_solve_kernel<<<solve_blocks, solve_threads>>>(y, out, n);
}

// round 2
// speedup vs baseline: 1.4320x; 1.4320x over previous
#include <cuda_runtime.h>

// Inverse of phi(t) = sum_k w_k exp(-s_k t) via precomputed cubic-Hermite
// inverse table + interpolation.
//
// Build: one warp per knot (K == 32 == warpSize, one component per lane),
//   log-space Newton on F(t) = ln phi(t) - ln y (convex -> monotone after
//   one overshoot, quadratic convergence). Stores (t*, dt/dy = 1/phi').
// Solve: each block converts knots -> per-interval cubic coefficients in
//   SHARED memory (one LDS.128 per point instead of two divergent L1 loads),
//   then grid-strides over y with float4 I/O. DRAM-bound by design.

#define NT 2048                 // intervals; knots = NT+1
#define Y0 0.05f
#define Y1 0.95f
#define DY  ((Y1 - Y0) / (float)NT)
#define INV_DY ((float)NT / (Y1 - Y0))
#define NEWTON_ITERS 14

__device__ float2 g_knots[NT + 1];

__global__ void __launch_bounds__(256)
phiinv_build_kernel(const float* __restrict__ w_logits,
                    const float* __restrict__ s_raw) {
    const int lane = threadIdx.x & 31;
    const int warp = (blockIdx.x * blockDim.x + threadIdx.x) >> 5;
    if (warp > NT) return;    // whole warps exit together

    // per-lane mixture params: softmax weight, softplus(+0.1) rate
    float lw = w_logits[lane];
    float m = lw;
    #pragma unroll
    for (int o = 16; o; o >>= 1) m = fmaxf(m, __shfl_xor_sync(0xffffffffu, m, o));
    float ew = __expf(lw - m);
    float wsum = ew;
    #pragma unroll
    for (int o = 16; o; o >>= 1) wsum += __shfl_xor_sync(0xffffffffu, wsum, o);
    float w = ew / wsum;

    float x = s_raw[lane];
    float s = fmaxf(x, 0.0f) + log1pf(__expf(-fabsf(x))) + 0.1f;

    const float yt = Y0 + (float)warp * DY;
    const float ly = __logf(yt);

    float t = 0.0f;
    #pragma unroll 1
    for (int it = 0; it < NEWTON_ITERS; ++it) {
        float ek = __expf(-t * s);
        float a = w * ek;        // -> f  = phi(t)
        float b = a * s;         // -> -phi'(t) > 0
        #pragma unroll
        for (int o = 16; o; o >>= 1) {
            a += __shfl_xor_sync(0xffffffffu, a, o);
            b += __shfl_xor_sync(0xffffffffu, b, o);
        }
        float g = __logf(a) - ly;              // F(t)
        t = fmaxf(fmaf(g, a / b, t), 0.0f);    // t - F/F' ; F' = -b/a
    }

    // final derivative at the converged root
    float ek = __expf(-t * s);
    float b = w * ek * s;
    #pragma unroll
    for (int o = 16; o; o >>= 1) b += __shfl_xor_sync(0xffffffffu, b, o);
    if (lane == 0)
        g_knots[warp] = make_float2(t, -1.0f / b);   // dt/dy = 1/phi' = -1/b
}

__global__ void __launch_bounds__(512)
phiinv_solve_kernel(const float4* __restrict__ y4,
                    float4* __restrict__ out4, int n4) {
    __shared__ float4 coef[NT];

    // knots -> per-interval cubic coefficients (Hermite, local fr in [0,1])
    for (int j = threadIdx.x; j < NT; j += blockDim.x) {
        float2 A = g_knots[j];
        float2 B = g_knots[j + 1];
        float c0 = A.x;
        float d0 = DY * A.y;
        float d1 = DY * B.y;
        float dt = B.x - A.x;
        float c2 = 3.0f * dt - 2.0f * d0 - d1;
        float c3 = -2.0f * dt + d0 + d1;
        coef[j] = make_float4(c0, d0, c2, c3);
    }
    __syncthreads();

    const int stride = gridDim.x * blockDim.x;
    for (int i = blockIdx.x * blockDim.x + threadIdx.x; i < n4; i += stride) {
        float4 yv = y4[i];
        float yy[4] = {yv.x, yv.y, yv.z, yv.w};
        float r[4];
        #pragma unroll
        for (int c = 0; c < 4; ++c) {
            float u = (yy[c] - Y0) * INV_DY;
            u = fminf(fmaxf(u, 0.0f), (float)NT - 0.5f);
            int j = (int)u;
            j = min(j, NT - 1);
            float fr = u - (float)j;
            float4 cf = coef[j];
            r[c] = fmaf(fmaf(fmaf(cf.w, fr, cf.z), fr, cf.y), fr, cf.x);
        }
        out4[i] = make_float4(r[0], r[1], r[2], r[3]);
    }
}

extern "C" void kernel_launch(void* const* d_in, const int* in_sizes, int n_in,
                              void* d_out, int out_size) {
    // y is the large input; the two size-K inputs keep metadata order.
    int yi = 0;
    for (int i = 1; i < n_in; ++i)
        if (in_sizes[i] > in_sizes[yi]) yi = i;
    int small[2], ns = 0;
    for (int i = 0; i < n_in && ns < 2; ++i)
        if (i != yi) small[ns++] = i;

    const float* y  = (const float*)d_in[yi];
    const float* wl = (const float*)d_in[small[0]];
    const float* sr = (const float*)d_in[small[1]];
    float* out = (float*)d_out;
    const int n = in_sizes[yi];

    // Build inverse table: NT+1 warps
    const int bt = 256;
    const int bb = ((NT + 1) * 32 + bt - 1) / bt;
    phiinv_build_kernel<<<bb, bt>>>(wl, sr);

    // Interpolate: float4 I/O, grid-stride, ~2 blocks per SM
    const int n4 = n / 4;             // N = 2M, divisible by 4
    const int st = 512;
    int sb = 304;                     // 2 x 152 SMs
    int need = (n4 + st - 1) / st;
    if (sb > need) sb = need;
    phiinv_solve_kernel<<<sb, st>>>((const float4*)y, (float4*)out, n4);
}

// round 3
// speedup vs baseline: 1.6290x; 1.1376x over previous
#include <cuda_runtime.h>

// Inverse of phi(t) = sum_k w_k exp(-s_k t) via small cubic-Hermite inverse
// table + interpolation.
//
// Build: one warp per knot (K == 32 == warpSize, one component per lane),
//   log-space Newton on F(t) = ln phi(t) - ln y (convex -> quadratic
//   convergence). Stores (t*, dt/dy = 1/phi').
// Solve: 8KB per-interval cubic coefficient table in shared memory ->
//   8 blocks/SM, 100% occupancy; one LDS.128 per point. DRAM-bound target.

#define NT 512                  // intervals; knots = NT+1
#define Y0 0.05f
#define Y1 0.95f
#define DY  ((Y1 - Y0) / (float)NT)
#define INV_DY ((float)NT / (Y1 - Y0))
#define NEWTON_ITERS 10

__device__ float2 g_knots[NT + 1];

__global__ void __launch_bounds__(256)
phiinv_build_kernel(const float* __restrict__ w_logits,
                    const float* __restrict__ s_raw) {
    const int lane = threadIdx.x & 31;
    const int warp = (blockIdx.x * blockDim.x + threadIdx.x) >> 5;
    if (warp > NT) return;    // whole warps exit together

    // per-lane mixture params: softmax weight, softplus(+0.1) rate
    float lw = w_logits[lane];
    float m = lw;
    #pragma unroll
    for (int o = 16; o; o >>= 1) m = fmaxf(m, __shfl_xor_sync(0xffffffffu, m, o));
    float ew = __expf(lw - m);
    float wsum = ew;
    #pragma unroll
    for (int o = 16; o; o >>= 1) wsum += __shfl_xor_sync(0xffffffffu, wsum, o);
    float w = ew / wsum;

    float x = s_raw[lane];
    float s = fmaxf(x, 0.0f) + log1pf(__expf(-fabsf(x))) + 0.1f;

    const float yt = Y0 + (float)warp * DY;
    const float ly = __logf(yt);

    float t = 0.0f;
    #pragma unroll 1
    for (int it = 0; it < NEWTON_ITERS; ++it) {
        float ek = __expf(-t * s);
        float a = w * ek;        // -> f  = phi(t)
        float b = a * s;         // -> -phi'(t) > 0
        #pragma unroll
        for (int o = 16; o; o >>= 1) {
            a += __shfl_xor_sync(0xffffffffu, a, o);
            b += __shfl_xor_sync(0xffffffffu, b, o);
        }
        float g = __logf(a) - ly;              // F(t) = ln f - ln y
        t = fmaxf(fmaf(g, a / b, t), 0.0f);    // t - F/F' ; F' = -b/a
    }

    // final derivative at the converged root
    float ek = __expf(-t * s);
    float b = w * ek * s;
    #pragma unroll
    for (int o = 16; o; o >>= 1) b += __shfl_xor_sync(0xffffffffu, b, o);
    if (lane == 0)
        g_knots[warp] = make_float2(t, -1.0f / b);   // dt/dy = 1/phi' = -1/b
}

__global__ void __launch_bounds__(256)
phiinv_solve_kernel(const float4* __restrict__ y4,
                    float4* __restrict__ out4, int n4) {
    __shared__ float4 coef[NT];

    // knots -> per-interval cubic coefficients (Hermite, local fr in [0,1])
    for (int j = threadIdx.x; j < NT; j += blockDim.x) {
        float2 A = g_knots[j];
        float2 B = g_knots[j + 1];
        float c0 = A.x;
        float d0 = DY * A.y;
        float d1 = DY * B.y;
        float dt = B.x - A.x;
        float c2 = 3.0f * dt - 2.0f * d0 - d1;
        float c3 = -2.0f * dt + d0 + d1;
        coef[j] = make_float4(c0, d0, c2, c3);
    }
    __syncthreads();

    const int stride = gridDim.x * blockDim.x;
    for (int i = blockIdx.x * blockDim.x + threadIdx.x; i < n4; i += stride) {
        float4 yv = y4[i];
        float yy[4] = {yv.x, yv.y, yv.z, yv.w};
        float r[4];
        #pragma unroll
        for (int c = 0; c < 4; ++c) {
            float u = (yy[c] - Y0) * INV_DY;
            u = fminf(fmaxf(u, 0.0f), (float)NT - 0.5f);
            int j = (int)u;
            float fr = u - (float)j;
            float4 cf = coef[j];
            r[c] = fmaf(fmaf(fmaf(cf.w, fr, cf.z), fr, cf.y), fr, cf.x);
        }
        out4[i] = make_float4(r[0], r[1], r[2], r[3]);
    }
}

extern "C" void kernel_launch(void* const* d_in, const int* in_sizes, int n_in,
                              void* d_out, int out_size) {
    // y is the large input; the two size-K inputs keep metadata order.
    int yi = 0;
    for (int i = 1; i < n_in; ++i)
        if (in_sizes[i] > in_sizes[yi]) yi = i;
    int small[2], ns = 0;
    for (int i = 0; i < n_in && ns < 2; ++i)
        if (i != yi) small[ns++] = i;

    const float* y  = (const float*)d_in[yi];
    const float* wl = (const float*)d_in[small[0]];
    const float* sr = (const float*)d_in[small[1]];
    float* out = (float*)d_out;
    const int n = in_sizes[yi];

    // Build inverse table: NT+1 warps
    const int bt = 256;
    const int bb = ((NT + 1) * 32 + bt - 1) / bt;
    phiinv_build_kernel<<<bb, bt>>>(wl, sr);

    // Interpolate: float4 I/O, 8 blocks/SM (8KB smem -> 100% occupancy)
    const int n4 = n / 4;             // N = 2M, divisible by 4
    const int st = 256;
    int sb = 1216;                    // 8 x 152 SMs, single wave
    int need = (n4 + st - 1) / st;
    if (sb > need) sb = need;
    phiinv_solve_kernel<<<sb, st>>>((const float4*)y, (float4*)out, n4);
}